// round 9
// baseline (speedup 1.0000x reference)
#include <cuda_runtime.h>
#include <math.h>

#define B_  8
#define SL  4096
#define D_  128
#define NH  8
#define NB  64         // buckets per hash
#define NC  512        // chunks per batch
#define TOT (NH*SL)
#define MNEG (-3.402823466e38f)

// ---------------- packed f32x2 helpers (sm_103a FFMA2) ----------------
__device__ __forceinline__ unsigned long long pack2(float lo, float hi) {
    unsigned long long r;
    asm("mov.b64 %0,{%1,%2};" : "=l"(r) : "f"(lo), "f"(hi));
    return r;
}
__device__ __forceinline__ void fma2(unsigned long long& d,
                                     unsigned long long a, unsigned long long b) {
    asm("fma.rn.f32x2 %0, %1, %2, %0;" : "+l"(d) : "l"(a), "l"(b));
}
__device__ __forceinline__ float2 unpack2(unsigned long long v) {
    float2 r;
    asm("mov.b64 {%0,%1}, %2;" : "=f"(r.x), "=f"(r.y) : "l"(v));
    return r;
}

// ---------------- device scratch ----------------
__device__ int            g_bucket[B_*NH*SL];
__device__ int            g_st    [B_*TOT];
__device__ int            g_sb    [B_*TOT];
__device__ unsigned short g_keys  [B_*SL*NH];   // (bucket_loc<<7)|chunk_loc per (token,hash)
__device__ float          g_osc   [(size_t)B_*NH*SL*D_];
__device__ float          g_lse   [B_*NH*SL];

// ---------------- K1: LSH hashing ----------------
__global__ void k_hash(const float* __restrict__ qk, const float* __restrict__ rot)
{
    __shared__ float qst[128*33];
    __shared__ float rs [128*32];
    __shared__ float rt [32*33];

    int b   = blockIdx.y;
    int s0  = blockIdx.x * 32;
    int tid = threadIdx.x;

    const float* qbase = qk + ((size_t)b*SL + s0) * D_;
    for (int i = tid; i < 32*128; i += 256) {
        int s = i >> 7, d = i & 127;
        qst[d*33 + s] = qbase[i];
    }

    for (int h = 0; h < NH; h++) {
        for (int i = tid; i < 128*32; i += 256) {
            int d = i >> 5, n = i & 31;
            rs[d*32 + n] = rot[d*(NH*32) + h*32 + n];
        }
        __syncthreads();

        int s = tid & 31, ng = tid >> 5;
        unsigned long long a01 = 0ull, a23 = 0ull;
        #pragma unroll 4
        for (int d = 0; d < 128; d++) {
            float q = qst[d*33 + s];
            unsigned long long qq = pack2(q, q);
            unsigned long long b01 = *(const unsigned long long*)&rs[d*32 + ng*4];
            unsigned long long b23 = *(const unsigned long long*)&rs[d*32 + ng*4 + 2];
            fma2(a01, qq, b01);
            fma2(a23, qq, b23);
        }
        float2 p01 = unpack2(a01), p23 = unpack2(a23);
        rt[s*33 + ng*4 + 0] = p01.x;
        rt[s*33 + ng*4 + 1] = p01.y;
        rt[s*33 + ng*4 + 2] = p23.x;
        rt[s*33 + ng*4 + 3] = p23.y;
        __syncthreads();

        if (tid < 32) {
            int ss = tid;
            float best = -3.4e38f; int bi = 0;
            for (int idx = 0; idx < 64; idx++) {   // first-occurrence argmax
                float vv = (idx < 32) ? rt[ss*33 + idx] : -rt[ss*33 + idx - 32];
                if (vv > best) { best = vv; bi = idx; }
            }
            g_bucket[(b*NH + h)*SL + s0 + ss] = bi + h*NB;
        }
        __syncthreads();
    }
}

// ---------------- K2: stable counting sort per (b, h) ----------------
__global__ void k_sort()
{
    __shared__ unsigned char lb[SL];
    __shared__ int counts[NB];
    __shared__ int prefix[NB];
    __shared__ int running[NB];
    __shared__ int wcnt[8*NB];

    int bh = blockIdx.x;
    int b  = bh >> 3, h = bh & 7;
    int tid = threadIdx.x;
    int lane = tid & 31, w = tid >> 5;

    if (tid < NB) { counts[tid] = 0; running[tid] = 0; }
    __syncthreads();

    for (int p = tid; p < SL; p += 256) {
        int v = g_bucket[(b*NH + h)*SL + p] - h*NB;
        lb[p] = (unsigned char)v;
        atomicAdd(&counts[v], 1);
    }
    __syncthreads();

    if (tid == 0) {
        int s = 0;
        for (int i = 0; i < NB; i++) { prefix[i] = s; s += counts[i]; }
    }
    __syncthreads();

    for (int tile = 0; tile < SL/256; tile++) {
        wcnt[tid] = 0; wcnt[tid + 256] = 0;
        int p = tile*256 + tid;
        int v = lb[p];
        unsigned mask = __match_any_sync(0xffffffffu, v);
        int intra  = __popc(mask & ((1u << lane) - 1u));
        int cnt    = __popc(mask);
        int leader = ((__ffs(mask) - 1) == lane);
        int base   = running[v];
        __syncthreads();
        if (leader) wcnt[w*NB + v] = cnt;
        __syncthreads();
        int bw = 0;
        for (int wp = 0; wp < w; wp++) bw += wcnt[wp*NB + v];

        int destLocal   = prefix[v] + base + bw + intra;
        int destInBatch = h*SL + destLocal;
        int gdest       = b*TOT + destInBatch;
        g_st[gdest] = p;
        g_sb[gdest] = h*NB + v;
        // 13-bit key: bucket_local (6b) << 7 | chunk_local (0..63)
        g_keys[(b*SL + p)*NH + h] = (unsigned short)((v << 7) | (destLocal >> 6));

        if (leader) atomicAdd(&running[v], cnt);
        __syncthreads();
    }
}

// ---------------- K3: per-chunk attention (2 blocks/SM) ----------------
#define QT_PAD 66
#define KT_PAD 128
#define QT_SZ  (128*QT_PAD)
#define KT_SZ  (128*KT_PAD)
#define ATTN_SMEM_WORDS (QT_SZ + KT_SZ + 512 + 256 + 64 + 64 + 128 + 128 + 128 + 256 + 20)
#define ATTN_SMEM_BYTES (ATTN_SMEM_WORDS*4)

__global__ void __launch_bounds__(256, 2)
k_attn(const float* __restrict__ qk, const float* __restrict__ vv)
{
    extern __shared__ float sm[];
    float*        Qt   = sm;                         // [k][i] pad 66 (reused as Pt[j][i])
    float*        Kt   = Qt + QT_SZ;                 // [k][j] pad 128 raw K (reused as Vs[j][d])
    unsigned int* kk4  = (unsigned int*)(Kt + KT_SZ);// 128 * uint4 packed keys
    unsigned int* qk4  = kk4 + 512;                  // 64 * uint4
    int*          stq  = (int*)(qk4 + 256);          // 64
    int*          qbv  = stq + 64;                   // 64
    int*          stk  = qbv + 64;                   // 128
    int*          kbv  = stk + 128;                  // 128
    float*        invn = (float*)(kbv + 128);        // 128
    float*        nrm2 = invn + 128;                 // 256
    float*        logtab = nrm2 + 256;               // 17

    int b = blockIdx.y, c = blockIdx.x, r = c >> 6;
    int tid = threadIdx.x;

    if (tid < 64) {
        int slot = b*TOT + c*64 + tid;
        int p = g_st[slot]; stq[tid] = p; qbv[tid] = g_sb[slot];
        ((uint4*)qk4)[tid] = *(const uint4*)&g_keys[(b*SL + p)*NH];
    } else if (tid < 192) {
        int j  = tid - 64;
        int cc = (j < 64) ? c : ((c + NC - 1) & (NC - 1));
        int slot = b*TOT + cc*64 + (j & 63);
        int p = g_st[slot]; stk[j] = p; kbv[j] = g_sb[slot];
        ((uint4*)kk4)[j] = *(const uint4*)&g_keys[(b*SL + p)*NH];
    } else if (tid < 209) {
        int t = tid - 192;
        logtab[t] = logf((float)t + 1e-9f);
    }
    __syncthreads();

    const float* qkb = qk + (size_t)b*SL*D_;
    const float* vb  = vv + (size_t)b*SL*D_;
    for (int i = tid; i < 64*128; i += 256) {
        int row = i >> 7, d = i & 127;
        Qt[d*QT_PAD + row] = qkb[(size_t)stq[row]*D_ + d];
    }
    for (int i = tid; i < 128*128; i += 256) {
        int row = i >> 7, d = i & 127;
        Kt[d*KT_PAD + row] = qkb[(size_t)stk[row]*D_ + d];
    }
    __syncthreads();

    // key norms (normalization folded into logits later)
    {
        int j = tid & 127, half = tid >> 7;
        float ss = 0.f;
        #pragma unroll 4
        for (int d = half*64; d < half*64 + 64; d++) {
            float x = Kt[d*KT_PAD + j]; ss += x*x;
        }
        nrm2[tid] = ss;
    }
    __syncthreads();
    if (tid < 128)
        invn[tid] = rsqrtf(fmaxf(nrm2[tid] + nrm2[tid + 128], 1e-24f));
    __syncthreads();

    int ty = tid >> 4, tx = tid & 15;
    int i0 = ty*4;                     // rows i0..i0+3; cols 4tx + 64g + 2pp + half

    // ---- GEMM1: S = Q @ K^T (raw K; f32x2 packed; A LDS.64, B LDS.128) ----
    unsigned long long facc[4][4];     // [ii][2g+pp]
    #pragma unroll
    for (int ii = 0; ii < 4; ii++)
        #pragma unroll
        for (int mp = 0; mp < 4; mp++) facc[ii][mp] = 0ull;

    #pragma unroll 4
    for (int k = 0; k < 128; k++) {
        float2 ap = *(const float2*)&Qt[k*QT_PAD + i0];
        float2 aq = *(const float2*)&Qt[k*QT_PAD + i0 + 2];
        unsigned long long a0 = pack2(ap.x, ap.x);
        unsigned long long a1 = pack2(ap.y, ap.y);
        unsigned long long a2 = pack2(aq.x, aq.x);
        unsigned long long a3 = pack2(aq.y, aq.y);
        #pragma unroll
        for (int g = 0; g < 2; g++) {
            ulonglong2 bp = *(const ulonglong2*)&Kt[k*KT_PAD + 4*tx + 64*g];
            fma2(facc[0][2*g], a0, bp.x);  fma2(facc[0][2*g+1], a0, bp.y);
            fma2(facc[1][2*g], a1, bp.x);  fma2(facc[1][2*g+1], a1, bp.y);
            fma2(facc[2][2*g], a2, bp.x);  fma2(facc[2][2*g+1], a2, bp.y);
            fma2(facc[3][2*g], a3, bp.x);  fma2(facc[3][2*g+1], a3, bp.y);
        }
    }

    // ---- masks + dup correction (branchless, packed-key compares) ----
    const float SC = 0.08838834764831845f;  // 128^-0.5
    unsigned int qw0[4], qw1[4], qw2[4], qw3[4];
    int qtv[4], qbb[4];
    #pragma unroll
    for (int ii = 0; ii < 4; ii++) {
        uint4 t = ((uint4*)qk4)[i0 + ii];
        qw0[ii] = t.x; qw1[ii] = t.y; qw2[ii] = t.z; qw3[ii] = t.w;
        qtv[ii] = stq[i0 + ii]; qbb[ii] = qbv[i0 + ii];
    }

    float fv[4][8];
    float pm[4] = {MNEG, MNEG, MNEG, MNEG};
    #pragma unroll
    for (int jj = 0; jj < 8; jj++) {
        int g = jj >> 2, pp = (jj >> 1) & 1, half = jj & 1;
        int j  = 4*tx + 64*g + 2*pp + half;
        int kt = stk[j], kb = kbv[j];
        float scj = SC * invn[j];
        uint4 kw = ((uint4*)kk4)[j];
        unsigned int k2x = kw.x + 0x00010001u;
        unsigned int k2y = kw.y + 0x00010001u;
        unsigned int k2z = kw.z + 0x00010001u;
        unsigned int k2w = kw.w + 0x00010001u;
        #pragma unroll
        for (int ii = 0; ii < 4; ii++) {
            float2 pr = unpack2(facc[ii][2*g + pp]);
            float val = (half ? pr.y : pr.x) * scj;
            if (qtv[ii] <  kt) val = MNEG;          // causal
            if (qtv[ii] == kt) val = -10000.0f;     // self penalty
            if (qbb[ii] != kb) val = MNEG;          // bucket mask
            int cnt = __popc(__vcmpeq2(qw0[ii], kw.x) | __vcmpeq2(qw0[ii], k2x))
                    + __popc(__vcmpeq2(qw1[ii], kw.y) | __vcmpeq2(qw1[ii], k2y))
                    + __popc(__vcmpeq2(qw2[ii], kw.z) | __vcmpeq2(qw2[ii], k2z))
                    + __popc(__vcmpeq2(qw3[ii], kw.w) | __vcmpeq2(qw3[ii], k2w));
            val -= logtab[cnt >> 4];                // dup correction (exact)
            fv[ii][jj] = val;
            pm[ii] = fmaxf(pm[ii], val);
        }
    }

    // ---- softmax: half-warp shfl reductions (no barriers) ----
    #pragma unroll
    for (int ii = 0; ii < 4; ii++) {
        float m = pm[ii];
        m = fmaxf(m, __shfl_xor_sync(0xffffffffu, m, 1));
        m = fmaxf(m, __shfl_xor_sync(0xffffffffu, m, 2));
        m = fmaxf(m, __shfl_xor_sync(0xffffffffu, m, 4));
        m = fmaxf(m, __shfl_xor_sync(0xffffffffu, m, 8));
        pm[ii] = m;
    }
    float ps[4];
    #pragma unroll
    for (int ii = 0; ii < 4; ii++) {
        float s = 0.f;
        #pragma unroll
        for (int jj = 0; jj < 8; jj++) {
            float e = __expf(fv[ii][jj] - pm[ii]);
            fv[ii][jj] = e; s += e;
        }
        s += __shfl_xor_sync(0xffffffffu, s, 1);
        s += __shfl_xor_sync(0xffffffffu, s, 2);
        s += __shfl_xor_sync(0xffffffffu, s, 4);
        s += __shfl_xor_sync(0xffffffffu, s, 8);
        ps[ii] = s;
    }

    __syncthreads();   // all warps done reading Qt / Kt

    // probabilities into Qt as Pt[j][i]
    #pragma unroll
    for (int ii = 0; ii < 4; ii++) {
        float is = 1.0f / ps[ii];
        #pragma unroll
        for (int jj = 0; jj < 8; jj++) {
            int j = 4*tx + 64*(jj >> 2) + 2*((jj >> 1) & 1) + (jj & 1);
            Qt[j*QT_PAD + i0 + ii] = fv[ii][jj] * is;
        }
    }
    if (tx == 0) {
        #pragma unroll
        for (int ii = 0; ii < 4; ii++)
            g_lse[(b*NH + r)*SL + stq[i0 + ii]] = pm[ii] + __logf(ps[ii]);
    }

    // V gather into the K-tile buffer (row-major [j][d])
    float* Vs = Kt;
    for (int i = tid; i < 128*32; i += 256) {
        int row = i >> 5, d4 = i & 31;
        float4 v4 = ((const float4*)(vb + (size_t)stk[row]*D_))[d4];
        ((float4*)(Vs + row*128))[d4] = v4;
    }
    __syncthreads();

    // ---- GEMM2: O = P @ V ----
    unsigned long long oacc[4][4];
    #pragma unroll
    for (int ii = 0; ii < 4; ii++)
        #pragma unroll
        for (int mp = 0; mp < 4; mp++) oacc[ii][mp] = 0ull;

    #pragma unroll 4
    for (int j = 0; j < 128; j++) {
        float2 ap = *(const float2*)&Qt[j*QT_PAD + i0];
        float2 aq = *(const float2*)&Qt[j*QT_PAD + i0 + 2];
        unsigned long long a0 = pack2(ap.x, ap.x);
        unsigned long long a1 = pack2(ap.y, ap.y);
        unsigned long long a2 = pack2(aq.x, aq.x);
        unsigned long long a3 = pack2(aq.y, aq.y);
        #pragma unroll
        for (int g = 0; g < 2; g++) {
            ulonglong2 bp = *(const ulonglong2*)&Vs[j*128 + 4*tx + 64*g];
            fma2(oacc[0][2*g], a0, bp.x);  fma2(oacc[0][2*g+1], a0, bp.y);
            fma2(oacc[1][2*g], a1, bp.x);  fma2(oacc[1][2*g+1], a1, bp.y);
            fma2(oacc[2][2*g], a2, bp.x);  fma2(oacc[2][2*g+1], a2, bp.y);
            fma2(oacc[3][2*g], a3, bp.x);  fma2(oacc[3][2*g+1], a3, bp.y);
        }
    }

    float* ob = g_osc + (size_t)((b*NH + r)*SL) * D_;
    #pragma unroll
    for (int ii = 0; ii < 4; ii++) {
        int p = stq[i0 + ii];
        #pragma unroll
        for (int g = 0; g < 2; g++) {
            float2 lo = unpack2(oacc[ii][2*g]);
            float2 hi = unpack2(oacc[ii][2*g + 1]);
            float4 o4 = make_float4(lo.x, lo.y, hi.x, hi.y);
            *(float4*)&ob[(size_t)p*D_ + 4*tx + 64*g] = o4;
        }
    }
}

// ---------------- K4: combine hash rounds ----------------
__global__ void k_combine(float* __restrict__ out)
{
    int idx = blockIdx.x*256 + threadIdx.x;
    int c4  = idx & 31;
    int p   = (idx >> 5) & (SL - 1);
    int b   = idx >> 17;

    float l[8]; float m = MNEG;
    #pragma unroll
    for (int r = 0; r < NH; r++) {
        l[r] = g_lse[(b*NH + r)*SL + p];
        m = fmaxf(m, l[r]);
    }
    float w[8]; float s = 0.f;
    #pragma unroll
    for (int r = 0; r < NH; r++) { w[r] = __expf(l[r] - m); s += w[r]; }
    float inv = 1.0f / s;

    float4 acc = make_float4(0.f, 0.f, 0.f, 0.f);
    #pragma unroll
    for (int r = 0; r < NH; r++) {
        const float4* op = (const float4*)(g_osc + (size_t)((b*NH + r)*SL + p)*D_);
        float4 v4 = op[c4];
        float wr = w[r] * inv;
        acc.x += wr*v4.x; acc.y += wr*v4.y; acc.z += wr*v4.z; acc.w += wr*v4.w;
    }
    ((float4*)out)[idx] = acc;
}

// ---------------- launcher ----------------
extern "C" void kernel_launch(void* const* d_in, const int* in_sizes, int n_in,
                              void* d_out, int out_size)
{
    const float* qk  = (const float*)d_in[0];
    const float* v   = (const float*)d_in[1];
    const float* rot = (const float*)d_in[2];
    float* out = (float*)d_out;

    cudaFuncSetAttribute(k_attn, cudaFuncAttributeMaxDynamicSharedMemorySize,
                         ATTN_SMEM_BYTES);

    k_hash<<<dim3(SL/32, B_), 256>>>(qk, rot);
    k_sort<<<B_*NH, 256>>>();
    k_attn<<<dim3(NC, B_), 256, ATTN_SMEM_BYTES>>>(qk, v);
    k_combine<<<(B_*SL*32)/256, 256>>>(out);
}

// round 14
// speedup vs baseline: 1.1500x; 1.1500x over previous
#include <cuda_runtime.h>
#include <math.h>

#define B_  8
#define SL  4096
#define D_  128
#define NH  8
#define NB  64         // buckets per hash
#define NC  512        // chunks per batch
#define TOT (NH*SL)
#define MNEG (-3.402823466e38f)

// ---------------- packed f32x2 helpers (sm_103a FFMA2) ----------------
__device__ __forceinline__ unsigned long long pack2(float lo, float hi) {
    unsigned long long r;
    asm("mov.b64 %0,{%1,%2};" : "=l"(r) : "f"(lo), "f"(hi));
    return r;
}
__device__ __forceinline__ void fma2(unsigned long long& d,
                                     unsigned long long a, unsigned long long b) {
    asm("fma.rn.f32x2 %0, %1, %2, %0;" : "+l"(d) : "l"(a), "l"(b));
}
__device__ __forceinline__ float2 unpack2(unsigned long long v) {
    float2 r;
    asm("mov.b64 {%0,%1}, %2;" : "=f"(r.x), "=f"(r.y) : "l"(v));
    return r;
}

// ---------------- device scratch ----------------
__device__ int            g_bucket[B_*NH*SL];
__device__ int            g_st    [B_*TOT];
__device__ int            g_sb    [B_*TOT];
__device__ unsigned short g_keys  [B_*SL*NH];   // (bucket_loc<<7)|chunk_loc per (token,hash)
__device__ float          g_osc   [(size_t)B_*NH*SL*D_];
__device__ float          g_lse   [B_*NH*SL];

// ---------------- K1: LSH hashing ----------------
__global__ void k_hash(const float* __restrict__ qk, const float* __restrict__ rot)
{
    __shared__ float qst[128*33];
    __shared__ float rs [128*32];
    __shared__ float rt [32*33];

    int b   = blockIdx.y;
    int s0  = blockIdx.x * 32;
    int tid = threadIdx.x;

    const float* qbase = qk + ((size_t)b*SL + s0) * D_;
    for (int i = tid; i < 32*128; i += 256) {
        int s = i >> 7, d = i & 127;
        qst[d*33 + s] = qbase[i];
    }

    for (int h = 0; h < NH; h++) {
        for (int i = tid; i < 128*32; i += 256) {
            int d = i >> 5, n = i & 31;
            rs[d*32 + n] = rot[d*(NH*32) + h*32 + n];
        }
        __syncthreads();

        int s = tid & 31, ng = tid >> 5;
        unsigned long long a01 = 0ull, a23 = 0ull;
        #pragma unroll 4
        for (int d = 0; d < 128; d++) {
            float q = qst[d*33 + s];
            unsigned long long qq = pack2(q, q);
            unsigned long long b01 = *(const unsigned long long*)&rs[d*32 + ng*4];
            unsigned long long b23 = *(const unsigned long long*)&rs[d*32 + ng*4 + 2];
            fma2(a01, qq, b01);
            fma2(a23, qq, b23);
        }
        float2 p01 = unpack2(a01), p23 = unpack2(a23);
        rt[s*33 + ng*4 + 0] = p01.x;
        rt[s*33 + ng*4 + 1] = p01.y;
        rt[s*33 + ng*4 + 2] = p23.x;
        rt[s*33 + ng*4 + 3] = p23.y;
        __syncthreads();

        if (tid < 32) {
            int ss = tid;
            float best = -3.4e38f; int bi = 0;
            for (int idx = 0; idx < 64; idx++) {   // first-occurrence argmax
                float vv = (idx < 32) ? rt[ss*33 + idx] : -rt[ss*33 + idx - 32];
                if (vv > best) { best = vv; bi = idx; }
            }
            g_bucket[(b*NH + h)*SL + s0 + ss] = bi + h*NB;
        }
        __syncthreads();
    }
}

// ---------------- K2: stable counting sort per (b, h) ----------------
__global__ void k_sort()
{
    __shared__ unsigned char lb[SL];
    __shared__ int counts[NB];
    __shared__ int prefix[NB];
    __shared__ int running[NB];
    __shared__ int wcnt[8*NB];

    int bh = blockIdx.x;
    int b  = bh >> 3, h = bh & 7;
    int tid = threadIdx.x;
    int lane = tid & 31, w = tid >> 5;

    if (tid < NB) { counts[tid] = 0; running[tid] = 0; }
    __syncthreads();

    for (int p = tid; p < SL; p += 256) {
        int v = g_bucket[(b*NH + h)*SL + p] - h*NB;
        lb[p] = (unsigned char)v;
        atomicAdd(&counts[v], 1);
    }
    __syncthreads();

    if (tid == 0) {
        int s = 0;
        for (int i = 0; i < NB; i++) { prefix[i] = s; s += counts[i]; }
    }
    __syncthreads();

    for (int tile = 0; tile < SL/256; tile++) {
        wcnt[tid] = 0; wcnt[tid + 256] = 0;
        int p = tile*256 + tid;
        int v = lb[p];
        unsigned mask = __match_any_sync(0xffffffffu, v);
        int intra  = __popc(mask & ((1u << lane) - 1u));
        int cnt    = __popc(mask);
        int leader = ((__ffs(mask) - 1) == lane);
        int base   = running[v];
        __syncthreads();
        if (leader) wcnt[w*NB + v] = cnt;
        __syncthreads();
        int bw = 0;
        for (int wp = 0; wp < w; wp++) bw += wcnt[wp*NB + v];

        int destLocal   = prefix[v] + base + bw + intra;
        int destInBatch = h*SL + destLocal;
        int gdest       = b*TOT + destInBatch;
        g_st[gdest] = p;
        g_sb[gdest] = h*NB + v;
        // 13-bit key: bucket_local (6b) << 7 | chunk_local (0..63)
        g_keys[(b*SL + p)*NH + h] = (unsigned short)((v << 7) | (destLocal >> 6));

        if (leader) atomicAdd(&running[v], cnt);
        __syncthreads();
    }
}

// ---------------- K3: per-chunk attention (2 blocks/SM) ----------------
#define QT_PAD 66
#define KT_PAD 130
#define QT_SZ  (128*QT_PAD)
#define KT_SZ  (128*KT_PAD)
#define ATTN_SMEM_WORDS (QT_SZ + KT_SZ + 512 + 256 + 64 + 64 + 128 + 128 + 128 + 256 + 20)
#define ATTN_SMEM_BYTES (ATTN_SMEM_WORDS*4)

__global__ void __launch_bounds__(256, 2)
k_attn(const float* __restrict__ qk, const float* __restrict__ vv)
{
    extern __shared__ float sm[];
    float*        Qt   = sm;                         // [k][i] pad 66 (reused as Pt[j][i])
    float*        Kt   = Qt + QT_SZ;                 // [k][j] pad 130 raw K (reused as Vs[j][d])
    unsigned int* kk4  = (unsigned int*)(Kt + KT_SZ);// 128 * uint4 packed keys
    unsigned int* qk4  = kk4 + 512;                  // 64 * uint4
    int*          stq  = (int*)(qk4 + 256);          // 64
    int*          qbv  = stq + 64;                   // 64
    int*          stk  = qbv + 64;                   // 128
    int*          kbv  = stk + 128;                  // 128
    float*        invn = (float*)(kbv + 128);        // 128
    float*        nrm2 = invn + 128;                 // 256
    float*        logtab = nrm2 + 256;               // 17

    int b = blockIdx.y, c = blockIdx.x, r = c >> 6;
    int tid = threadIdx.x;

    if (tid < 64) {
        int slot = b*TOT + c*64 + tid;
        int p = g_st[slot]; stq[tid] = p; qbv[tid] = g_sb[slot];
        ((uint4*)qk4)[tid] = *(const uint4*)&g_keys[(b*SL + p)*NH];
    } else if (tid < 192) {
        int j  = tid - 64;
        int cc = (j < 64) ? c : ((c + NC - 1) & (NC - 1));
        int slot = b*TOT + cc*64 + (j & 63);
        int p = g_st[slot]; stk[j] = p; kbv[j] = g_sb[slot];
        ((uint4*)kk4)[j] = *(const uint4*)&g_keys[(b*SL + p)*NH];
    } else if (tid < 209) {
        int t = tid - 192;
        logtab[t] = logf((float)t + 1e-9f);
    }
    __syncthreads();

    const float* qkb = qk + (size_t)b*SL*D_;
    const float* vb  = vv + (size_t)b*SL*D_;
    for (int i = tid; i < 64*128; i += 256) {
        int row = i >> 7, d = i & 127;
        Qt[d*QT_PAD + row] = qkb[(size_t)stq[row]*D_ + d];
    }
    for (int i = tid; i < 128*128; i += 256) {
        int row = i >> 7, d = i & 127;
        Kt[d*KT_PAD + row] = qkb[(size_t)stk[row]*D_ + d];
    }
    __syncthreads();

    // key norms (normalization folded into logits later)
    {
        int j = tid & 127, half = tid >> 7;
        float ss = 0.f;
        #pragma unroll 4
        for (int d = half*64; d < half*64 + 64; d++) {
            float x = Kt[d*KT_PAD + j]; ss += x*x;
        }
        nrm2[tid] = ss;
    }
    __syncthreads();
    if (tid < 128)
        invn[tid] = rsqrtf(fmaxf(nrm2[tid] + nrm2[tid + 128], 1e-24f));
    __syncthreads();

    int ty = tid >> 4, tx = tid & 15;
    int i0 = ty*4;                     // rows i0..i0+3; cols 2tx + 32mp (+1)

    // ---- GEMM1: S = Q @ K^T (raw K; A 2x LDS.64, B 4x LDS.64) ----
    unsigned long long facc[4][4];
    #pragma unroll
    for (int ii = 0; ii < 4; ii++)
        #pragma unroll
        for (int mp = 0; mp < 4; mp++) facc[ii][mp] = 0ull;

    #pragma unroll 4
    for (int k = 0; k < 128; k++) {
        float2 ap = *(const float2*)&Qt[k*QT_PAD + i0];
        float2 aq = *(const float2*)&Qt[k*QT_PAD + i0 + 2];
        unsigned long long a0 = pack2(ap.x, ap.x);
        unsigned long long a1 = pack2(ap.y, ap.y);
        unsigned long long a2 = pack2(aq.x, aq.x);
        unsigned long long a3 = pack2(aq.y, aq.y);
        #pragma unroll
        for (int mp = 0; mp < 4; mp++) {
            unsigned long long bp =
                *(const unsigned long long*)&Kt[k*KT_PAD + 2*tx + 32*mp];
            fma2(facc[0][mp], a0, bp);
            fma2(facc[1][mp], a1, bp);
            fma2(facc[2][mp], a2, bp);
            fma2(facc[3][mp], a3, bp);
        }
    }

    // ---- masks + dup correction (branchless, packed-key compares) ----
    const float SC = 0.08838834764831845f;  // 128^-0.5
    unsigned int qw0[4], qw1[4], qw2[4], qw3[4];
    int qtv[4], qbb[4];
    #pragma unroll
    for (int ii = 0; ii < 4; ii++) {
        uint4 t = ((uint4*)qk4)[i0 + ii];
        qw0[ii] = t.x; qw1[ii] = t.y; qw2[ii] = t.z; qw3[ii] = t.w;
        qtv[ii] = stq[i0 + ii]; qbb[ii] = qbv[i0 + ii];
    }

    float fv[4][8];
    float pm[4] = {MNEG, MNEG, MNEG, MNEG};
    #pragma unroll
    for (int jj = 0; jj < 8; jj++) {
        int mp = jj >> 1, half = jj & 1;
        int j  = 2*tx + 32*mp + half;
        int kt = stk[j], kb = kbv[j];
        float scj = SC * invn[j];
        uint4 kw = ((uint4*)kk4)[j];
        unsigned int k2x = kw.x + 0x00010001u;
        unsigned int k2y = kw.y + 0x00010001u;
        unsigned int k2z = kw.z + 0x00010001u;
        unsigned int k2w = kw.w + 0x00010001u;
        #pragma unroll
        for (int ii = 0; ii < 4; ii++) {
            float2 pr = unpack2(facc[ii][mp]);
            float val = (half ? pr.y : pr.x) * scj;
            if (qtv[ii] <  kt) val = MNEG;          // causal
            if (qtv[ii] == kt) val = -10000.0f;     // self penalty
            if (qbb[ii] != kb) val = MNEG;          // bucket mask
            int cnt = __popc(__vcmpeq2(qw0[ii], kw.x) | __vcmpeq2(qw0[ii], k2x))
                    + __popc(__vcmpeq2(qw1[ii], kw.y) | __vcmpeq2(qw1[ii], k2y))
                    + __popc(__vcmpeq2(qw2[ii], kw.z) | __vcmpeq2(qw2[ii], k2z))
                    + __popc(__vcmpeq2(qw3[ii], kw.w) | __vcmpeq2(qw3[ii], k2w));
            val -= logtab[cnt >> 4];                // dup correction (exact)
            fv[ii][jj] = val;
            pm[ii] = fmaxf(pm[ii], val);
        }
    }

    // ---- softmax: half-warp shfl reductions (no barriers) ----
    #pragma unroll
    for (int ii = 0; ii < 4; ii++) {
        float m = pm[ii];
        m = fmaxf(m, __shfl_xor_sync(0xffffffffu, m, 1));
        m = fmaxf(m, __shfl_xor_sync(0xffffffffu, m, 2));
        m = fmaxf(m, __shfl_xor_sync(0xffffffffu, m, 4));
        m = fmaxf(m, __shfl_xor_sync(0xffffffffu, m, 8));
        pm[ii] = m;
    }
    float ps[4];
    #pragma unroll
    for (int ii = 0; ii < 4; ii++) {
        float s = 0.f;
        #pragma unroll
        for (int jj = 0; jj < 8; jj++) {
            float e = __expf(fv[ii][jj] - pm[ii]);
            fv[ii][jj] = e; s += e;
        }
        s += __shfl_xor_sync(0xffffffffu, s, 1);
        s += __shfl_xor_sync(0xffffffffu, s, 2);
        s += __shfl_xor_sync(0xffffffffu, s, 4);
        s += __shfl_xor_sync(0xffffffffu, s, 8);
        ps[ii] = s;
    }

    __syncthreads();   // all warps done reading Qt / Kt

    // probabilities into Qt as Pt[j][i]
    #pragma unroll
    for (int ii = 0; ii < 4; ii++) {
        float is = 1.0f / ps[ii];
        #pragma unroll
        for (int jj = 0; jj < 8; jj++) {
            int j = 2*tx + 32*(jj >> 1) + (jj & 1);
            Qt[j*QT_PAD + i0 + ii] = fv[ii][jj] * is;
        }
    }
    if (tx == 0) {
        #pragma unroll
        for (int ii = 0; ii < 4; ii++)
            g_lse[(b*NH + r)*SL + stq[i0 + ii]] = pm[ii] + __logf(ps[ii]);
    }

    // V gather into the K-tile buffer (row-major [j][d])
    float* Vs = Kt;
    for (int i = tid; i < 128*32; i += 256) {
        int row = i >> 5, d4 = i & 31;
        float4 v4 = ((const float4*)(vb + (size_t)stk[row]*D_))[d4];
        ((float4*)(Vs + row*128))[d4] = v4;
    }
    __syncthreads();

    // ---- GEMM2: O = P @ V ----
    unsigned long long oacc[4][4];
    #pragma unroll
    for (int ii = 0; ii < 4; ii++)
        #pragma unroll
        for (int mp = 0; mp < 4; mp++) oacc[ii][mp] = 0ull;

    #pragma unroll 4
    for (int j = 0; j < 128; j++) {
        float2 ap = *(const float2*)&Qt[j*QT_PAD + i0];
        float2 aq = *(const float2*)&Qt[j*QT_PAD + i0 + 2];
        unsigned long long a0 = pack2(ap.x, ap.x);
        unsigned long long a1 = pack2(ap.y, ap.y);
        unsigned long long a2 = pack2(aq.x, aq.x);
        unsigned long long a3 = pack2(aq.y, aq.y);
        #pragma unroll
        for (int mp = 0; mp < 4; mp++) {
            unsigned long long bp =
                *(const unsigned long long*)&Vs[j*128 + 2*tx + 32*mp];
            fma2(oacc[0][mp], a0, bp);
            fma2(oacc[1][mp], a1, bp);
            fma2(oacc[2][mp], a2, bp);
            fma2(oacc[3][mp], a3, bp);
        }
    }

    float* ob = g_osc + (size_t)((b*NH + r)*SL) * D_;
    #pragma unroll
    for (int ii = 0; ii < 4; ii++) {
        int p = stq[i0 + ii];
        #pragma unroll
        for (int mp = 0; mp < 4; mp++) {
            float2 pr = unpack2(oacc[ii][mp]);
            *(float2*)&ob[(size_t)p*D_ + 2*tx + 32*mp] = pr;
        }
    }
}

// ---------------- K4: combine hash rounds ----------------
__global__ void k_combine(float* __restrict__ out)
{
    int idx = blockIdx.x*256 + threadIdx.x;
    int c4  = idx & 31;
    int p   = (idx >> 5) & (SL - 1);
    int b   = idx >> 17;

    float l[8]; float m = MNEG;
    #pragma unroll
    for (int r = 0; r < NH; r++) {
        l[r] = g_lse[(b*NH + r)*SL + p];
        m = fmaxf(m, l[r]);
    }
    float w[8]; float s = 0.f;
    #pragma unroll
    for (int r = 0; r < NH; r++) { w[r] = __expf(l[r] - m); s += w[r]; }
    float inv = 1.0f / s;

    float4 acc = make_float4(0.f, 0.f, 0.f, 0.f);
    #pragma unroll
    for (int r = 0; r < NH; r++) {
        const float4* op = (const float4*)(g_osc + (size_t)((b*NH + r)*SL + p)*D_);
        float4 v4 = op[c4];
        float wr = w[r] * inv;
        acc.x += wr*v4.x; acc.y += wr*v4.y; acc.z += wr*v4.z; acc.w += wr*v4.w;
    }
    ((float4*)out)[idx] = acc;
}

// ---------------- launcher ----------------
extern "C" void kernel_launch(void* const* d_in, const int* in_sizes, int n_in,
                              void* d_out, int out_size)
{
    const float* qk  = (const float*)d_in[0];
    const float* v   = (const float*)d_in[1];
    const float* rot = (const float*)d_in[2];
    float* out = (float*)d_out;

    cudaFuncSetAttribute(k_attn, cudaFuncAttributeMaxDynamicSharedMemorySize,
                         ATTN_SMEM_BYTES);

    k_hash<<<dim3(SL/32, B_), 256>>>(qk, rot);
    k_sort<<<B_*NH, 256>>>();
    k_attn<<<dim3(NC, B_), 256, ATTN_SMEM_BYTES>>>(qk, v);
    k_combine<<<(B_*SL*32)/256, 256>>>(out);
}